// round 8
// baseline (speedup 1.0000x reference)
#include <cuda_runtime.h>

#define TM    32      // batch rows per CTA
#define KB    8       // k-chunk staged in smem (double buffered)
#define NTHR  256

// Transposed mid weights: g_Wt[l][k][n] = Ws[l][n][k]  (512x512 each)
__device__ float g_Wt[6][512 * 512];

union f2u { float2 f; unsigned long long u; };

__device__ __forceinline__ void ffma2(f2u& d, const f2u& a, const f2u& b) {
    asm("fma.rn.f32x2 %0, %1, %2, %0;" : "+l"(d.u) : "l"(a.u), "l"(b.u));
}

__device__ __forceinline__ void cp_async16(float* dst_smem, const float* src_gmem) {
    unsigned s = (unsigned)__cvta_generic_to_shared(dst_smem);
    asm volatile("cp.async.cg.shared.global [%0], [%1], 16;" :: "r"(s), "l"(src_gmem));
}
__device__ __forceinline__ void cp_commit() { asm volatile("cp.async.commit_group;"); }
template<int N> __device__ __forceinline__ void cp_wait() {
    asm volatile("cp.async.wait_group %0;" :: "n"(N));
}

// output width of linear layer l (l = 0..6) for factor F
template<int F>
__host__ __device__ constexpr int hdim(int l) {
    return (F == 0) ? 256 : ((F == 2) ? 512 : ((l % 2 == 0) ? 512 : 256));
}

// smem layout (floats): act[TM*512] | Bs[2*KB*512] | red[2*32*2]
#define ACT_F   (TM * 512)
#define BS_F    (2 * KB * 512)
#define RED_F   (2 * 32 * 2)
#define SMEM_F  (ACT_F + BS_F + RED_F)

// ---------------- weight transpose prep ----------------
__global__ void prep_transpose(const float* __restrict__ Ws) {
    __shared__ float tile[32][33];
    int l  = blockIdx.z;
    int bk = blockIdx.x * 32;
    int bn = blockIdx.y * 32;
    int tx = threadIdx.x, ty = threadIdx.y;
    const float* W = Ws + l * 512 * 512;
    #pragma unroll
    for (int i = 0; i < 32; i += 8)
        tile[ty + i][tx] = W[(bn + ty + i) * 512 + bk + tx];
    __syncthreads();
    float* O = g_Wt[l];
    #pragma unroll
    for (int i = 0; i < 32; i += 8)
        O[(bk + ty + i) * 512 + bn + tx] = tile[tx][ty + i];
}

// ---------------- LN + ReLU epilogue (cross-half reduction) ----------------
// warp (cy, ry) owns rows [ry*8, ry*8+8) and cols [cy*HOUT/2, (cy+1)*HOUT/2)
template<int HOUT>
__device__ __forceinline__ void ln_relu_store(f2u (&acc)[8][HOUT / 128],
                                              const float* __restrict__ lw,
                                              const float* __restrict__ lb,
                                              float* act, float* red,
                                              int tx, int cy, int ry) {
    constexpr int J2 = HOUT / 128;
    const int n0 = cy * (HOUT / 2) + 2 * tx;

    float sr[8], qr[8];
    #pragma unroll
    for (int r = 0; r < 8; ++r) {
        float s = 0.f, q = 0.f;
        #pragma unroll
        for (int j = 0; j < J2; ++j) {
            float2 v = acc[r][j].f;
            s += v.x + v.y;
            q += v.x * v.x + v.y * v.y;
        }
        #pragma unroll
        for (int o = 16; o > 0; o >>= 1) {
            s += __shfl_xor_sync(0xffffffffu, s, o);
            q += __shfl_xor_sync(0xffffffffu, q, o);
        }
        sr[r] = s; qr[r] = q;
        if (tx == 0) {
            red[(cy * 32 + ry * 8 + r) * 2 + 0] = s;
            red[(cy * 32 + ry * 8 + r) * 2 + 1] = q;
        }
    }
    __syncthreads();

    float2 lwv[J2], lbv[J2];
    #pragma unroll
    for (int j = 0; j < J2; ++j) {
        lwv[j] = *reinterpret_cast<const float2*>(lw + n0 + 64 * j);
        lbv[j] = *reinterpret_cast<const float2*>(lb + n0 + 64 * j);
    }
    #pragma unroll
    for (int r = 0; r < 8; ++r) {
        const int rowg = ry * 8 + r;
        const float s = sr[r] + red[((cy ^ 1) * 32 + rowg) * 2 + 0];
        const float q = qr[r] + red[((cy ^ 1) * 32 + rowg) * 2 + 1];
        const float mean = s * (1.0f / HOUT);
        const float var  = q * (1.0f / HOUT) - mean * mean;
        const float rstd = rsqrtf(var + 1e-5f);
        float2* arow = reinterpret_cast<float2*>(act + rowg * 512 + n0);
        #pragma unroll
        for (int j = 0; j < J2; ++j) {
            float2 v = acc[r][j].f;
            float2 o2;
            o2.x = fmaxf((v.x - mean) * rstd * lwv[j].x + lbv[j].x, 0.f);
            o2.y = fmaxf((v.y - mean) * rstd * lwv[j].y + lbv[j].y, 0.f);
            arow[32 * j] = o2;
        }
    }
    __syncthreads();   // act ready; Bs/red safe for reuse
}

// ---------------- mid layer: act[TM x HIN] @ Wt -> LN -> ReLU -> act ----------------
template<int HIN, int HOUT>
__device__ __noinline__ void mid_layer(const float* __restrict__ Wt,
                                       const float* __restrict__ bias,
                                       const float* __restrict__ lw,
                                       const float* __restrict__ lb,
                                       int tid, int tx, int cy, int ry) {
    extern __shared__ float smem[];
    float* act = smem;
    float* Bs  = smem + ACT_F;
    float* red = smem + ACT_F + BS_F;

    constexpr int J2  = HOUT / 128;
    constexpr int NCH = HIN / KB;
    constexpr int NF4 = KB * HOUT / 4 / NTHR;

    const int n0 = cy * (HOUT / 2) + 2 * tx;

    f2u acc[8][J2];
    #pragma unroll
    for (int j = 0; j < J2; ++j) {
        float2 bv = *reinterpret_cast<const float2*>(bias + n0 + 64 * j);
        #pragma unroll
        for (int r = 0; r < 8; ++r) acc[r][j].f = bv;
    }

    // prefetch chunk 0
    #pragma unroll
    for (int t = 0; t < NF4; ++t) {
        int idx = (tid + t * NTHR) * 4;
        int kk  = idx / HOUT;
        int nf  = idx - kk * HOUT;
        cp_async16(Bs + kk * 512 + nf, Wt + kk * 512 + nf);
    }
    cp_commit();

    for (int c = 0; c < NCH; ++c) {
        cp_wait<0>();
        __syncthreads();      // chunk c visible; all warps done with buffer (c+1)&1
        if (c + 1 < NCH) {    // safe to overwrite (c+1)&1 now
            const float* src = Wt + (c + 1) * (KB * 512);
            float* dst = Bs + ((c + 1) & 1) * (KB * 512);
            #pragma unroll
            for (int t = 0; t < NF4; ++t) {
                int idx = (tid + t * NTHR) * 4;
                int kk  = idx / HOUT;
                int nf  = idx - kk * HOUT;
                cp_async16(dst + kk * 512 + nf, src + kk * 512 + nf);
            }
            cp_commit();
        }

        const float* B = Bs + (c & 1) * (KB * 512);
        const float* A = act + c * KB + (ry * 8) * 512;
        #pragma unroll
        for (int kp = 0; kp < KB / 2; ++kp) {
            float2 av[8];
            #pragma unroll
            for (int r = 0; r < 8; ++r)
                av[r] = *reinterpret_cast<const float2*>(A + r * 512 + 2 * kp);
            #pragma unroll
            for (int u = 0; u < 2; ++u) {
                f2u bv[J2];
                const float2* Brow = reinterpret_cast<const float2*>(B + (2 * kp + u) * 512 + n0);
                #pragma unroll
                for (int j = 0; j < J2; ++j) bv[j].f = Brow[32 * j];
                #pragma unroll
                for (int r = 0; r < 8; ++r) {
                    float a = u ? av[r].y : av[r].x;
                    f2u a2; a2.f = make_float2(a, a);
                    #pragma unroll
                    for (int j = 0; j < J2; ++j) ffma2(acc[r][j], a2, bv[j]);
                }
            }
        }
    }
    ln_relu_store<HOUT>(acc, lw, lb, act, red, tx, cy, ry);
}

// ---------------- first layer (K = 6) ----------------
template<int F>
__device__ __forceinline__ void layer0(const float* __restrict__ inputs,
                                       const float* __restrict__ W_in,
                                       const float* __restrict__ b_in,
                                       const float* __restrict__ lw,
                                       const float* __restrict__ lb,
                                       int tid, int tx, int cy, int ry, int rowbase) {
    extern __shared__ float smem[];
    float* act = smem;
    float* xin = smem + ACT_F;            // reuse Bs region
    float* red = smem + ACT_F + BS_F;
    constexpr int HOUT = hdim<F>(0);
    constexpr int J2 = HOUT / 128;
    const int n0 = cy * (HOUT / 2) + 2 * tx;

    if (tid < TM * 6) xin[tid] = inputs[rowbase * 6 + tid];
    __syncthreads();

    f2u acc[8][J2];
    #pragma unroll
    for (int j = 0; j < J2; ++j) {
        const int n = n0 + 64 * j;
        float2 w[6];
        #pragma unroll
        for (int k = 0; k < 6; ++k)
            w[k] = make_float2(W_in[n * 6 + k], W_in[(n + 1) * 6 + k]);
        float2 bb = make_float2(b_in[n], b_in[n + 1]);
        #pragma unroll
        for (int r = 0; r < 8; ++r) {
            const float* x = xin + (ry * 8 + r) * 6;
            float2 s = bb;
            #pragma unroll
            for (int k = 0; k < 6; ++k) { s.x += x[k] * w[k].x; s.y += x[k] * w[k].y; }
            acc[r][j].f = s;
        }
    }
    // xin reads complete before ln's first barrier; Bs reuse happens after ln's final barrier
    ln_relu_store<HOUT>(acc, lw, lb, act, red, tx, cy, ry);
}

// ---------------- output layer (3 outputs) ----------------
template<int HIN>
__device__ __forceinline__ void out_layer(const float* __restrict__ W_out,
                                          const float* __restrict__ b_out,
                                          float* __restrict__ out,
                                          int tx, int ty, int rowbase, int fidx) {
    extern __shared__ float smem[];
    const float* act = smem;
    float p[4][3];
    #pragma unroll
    for (int r = 0; r < 4; ++r) p[r][0] = p[r][1] = p[r][2] = 0.f;
    #pragma unroll
    for (int t = 0; t < HIN / 32; ++t) {
        int k = tx + 32 * t;
        float w0 = W_out[k], w1 = W_out[512 + k], w2 = W_out[1024 + k];
        #pragma unroll
        for (int r = 0; r < 4; ++r) {
            float a = act[(ty * 4 + r) * 512 + k];
            p[r][0] += a * w0; p[r][1] += a * w1; p[r][2] += a * w2;
        }
    }
    #pragma unroll
    for (int o = 16; o > 0; o >>= 1) {
        #pragma unroll
        for (int r = 0; r < 4; ++r) {
            p[r][0] += __shfl_xor_sync(0xffffffffu, p[r][0], o);
            p[r][1] += __shfl_xor_sync(0xffffffffu, p[r][1], o);
            p[r][2] += __shfl_xor_sync(0xffffffffu, p[r][2], o);
        }
    }
    if (tx == 0) {
        #pragma unroll
        for (int r = 0; r < 4; ++r) {
            int row = rowbase + ty * 4 + r;
            float* op = out + row * 9 + fidx * 3;
            op[0] = p[r][0] + b_out[0];
            op[1] = p[r][1] + b_out[1];
            op[2] = p[r][2] + b_out[2];
        }
    }
}

// ---------------- main fused kernel per factor ----------------
template<int F>
__global__ void __launch_bounds__(NTHR, 2) mipnet_kernel(
    const float* __restrict__ inputs,
    const float* __restrict__ W_in, const float* __restrict__ b_in,
    const float* __restrict__ bs,
    const float* __restrict__ ln_w, const float* __restrict__ ln_b,
    const float* __restrict__ W_out, const float* __restrict__ b_out,
    float* __restrict__ out)
{
    const int tid = threadIdx.x;
    const int tx  = tid & 31;
    const int wid = tid >> 5;
    const int cy  = wid & 1;     // column half
    const int ry  = wid >> 1;    // row group (8 rows)
    const int rowbase = blockIdx.x * TM;

    layer0<F>(inputs, W_in, b_in, ln_w, ln_b, tid, tx, cy, ry, rowbase);
    mid_layer<hdim<F>(0), hdim<F>(1)>(g_Wt[0], bs,        ln_w + 512,  ln_b + 512,  tid, tx, cy, ry);
    mid_layer<hdim<F>(1), hdim<F>(2)>(g_Wt[1], bs + 512,  ln_w + 1024, ln_b + 1024, tid, tx, cy, ry);
    mid_layer<hdim<F>(2), hdim<F>(3)>(g_Wt[2], bs + 1024, ln_w + 1536, ln_b + 1536, tid, tx, cy, ry);
    mid_layer<hdim<F>(3), hdim<F>(4)>(g_Wt[3], bs + 1536, ln_w + 2048, ln_b + 2048, tid, tx, cy, ry);
    mid_layer<hdim<F>(4), hdim<F>(5)>(g_Wt[4], bs + 2048, ln_w + 2560, ln_b + 2560, tid, tx, cy, ry);
    mid_layer<hdim<F>(5), hdim<F>(6)>(g_Wt[5], bs + 2560, ln_w + 3072, ln_b + 3072, tid, tx, cy, ry);
    out_layer<hdim<F>(6)>(W_out, b_out, out, tx, wid, rowbase, F);
}

extern "C" void kernel_launch(void* const* d_in, const int* in_sizes, int n_in,
                              void* d_out, int out_size) {
    const float* inputs = (const float*)d_in[0];
    const float* W_in   = (const float*)d_in[1];
    const float* b_in   = (const float*)d_in[2];
    const float* Ws     = (const float*)d_in[3];
    const float* bs     = (const float*)d_in[4];
    const float* ln_w   = (const float*)d_in[5];
    const float* ln_b   = (const float*)d_in[6];
    const float* W_out  = (const float*)d_in[7];
    const float* b_out  = (const float*)d_in[8];
    float* out = (float*)d_out;

    const int N = in_sizes[0] / 6;
    const int nblk = N / TM;

    {
        dim3 tb(32, 8), tg(16, 16, 6);
        prep_transpose<<<tg, tb>>>(Ws);
    }

    const int smem = SMEM_F * (int)sizeof(float);   // 98,816 B
    cudaFuncSetAttribute(mipnet_kernel<0>, cudaFuncAttributeMaxDynamicSharedMemorySize, smem);
    cudaFuncSetAttribute(mipnet_kernel<1>, cudaFuncAttributeMaxDynamicSharedMemorySize, smem);
    cudaFuncSetAttribute(mipnet_kernel<2>, cudaFuncAttributeMaxDynamicSharedMemorySize, smem);

    mipnet_kernel<0><<<nblk, NTHR, smem>>>(inputs, W_in, b_in, bs, ln_w, ln_b, W_out, b_out, out);
    mipnet_kernel<1><<<nblk, NTHR, smem>>>(inputs, W_in, b_in, bs, ln_w, ln_b, W_out, b_out, out);
    mipnet_kernel<2><<<nblk, NTHR, smem>>>(inputs, W_in, b_in, bs, ln_w, ln_b, W_out, b_out, out);
}

// round 10
// speedup vs baseline: 1.9284x; 1.9284x over previous
#include <cuda_runtime.h>
#include <cuda_bf16.h>
#include <cstdint>

#define NTHR 256
#define TMR  64

// Weight blob: [layer][kt][hl][n][pos] uint32 words.
//  kt = k16 chunk (0..31), hl = 0 hi / 1 lo, n = 0..511,
//  pos = interleave of k-pair index kpl (0..7): pos = 2*(kpl&3) + (kpl>>2)
//  so the mma B-fragment pair (kpl, kpl+4) is one contiguous 8B load.
__device__ __align__(16) uint32_t gW[6u * 32u * 8192u];   // 6 MB

// ---- smem byte offsets (total 212992 B) ----
#define SM_ACT_HI 0         // 16384 words
#define SM_ACT_LO 65536     // 16384 words
#define SM_WBUF   131072    // 2 x 8192 words
#define SM_BIAS   196608    // 512 f
#define SM_LW     198656    // 512 f
#define SM_LB     200704    // 512 f
#define SM_WOUT   202752    // 3*512 f
#define SM_RED    208896    // 2*64*2 f
#define SM_OUTACC 209920    // 2*64*3 f
#define SM_XIN    211456    // 64*6 f
#define SM_TOTAL  212992

__device__ __forceinline__ void cp16(void* dst, const void* src) {
    unsigned s = (unsigned)__cvta_generic_to_shared(dst);
    asm volatile("cp.async.cg.shared.global [%0], [%1], 16;" :: "r"(s), "l"(src));
}
__device__ __forceinline__ void cp_commit() { asm volatile("cp.async.commit_group;"); }
__device__ __forceinline__ void cp_wait0()  { asm volatile("cp.async.wait_group 0;"); }

__device__ __forceinline__ void mma_bf16(float& d0, float& d1, float& d2, float& d3,
                                         uint32_t a0, uint32_t a1, uint32_t a2, uint32_t a3,
                                         uint32_t b0, uint32_t b1) {
    asm volatile("mma.sync.aligned.m16n8k16.row.col.f32.bf16.bf16.f32 "
        "{%0,%1,%2,%3}, {%4,%5,%6,%7}, {%8,%9}, {%0,%1,%2,%3};"
        : "+f"(d0), "+f"(d1), "+f"(d2), "+f"(d3)
        : "r"(a0), "r"(a1), "r"(a2), "r"(a3), "r"(b0), "r"(b1));
}

__device__ __forceinline__ uint32_t pack_split(float a, float b, uint32_t& lo) {
    __nv_bfloat16 ha = __float2bfloat16(a), hb = __float2bfloat16(b);
    __nv_bfloat16 la = __float2bfloat16(a - __bfloat162float(ha));
    __nv_bfloat16 lb = __float2bfloat16(b - __bfloat162float(hb));
    lo = (uint32_t)__bfloat16_as_ushort(la) | ((uint32_t)__bfloat16_as_ushort(lb) << 16);
    return (uint32_t)__bfloat16_as_ushort(ha) | ((uint32_t)__bfloat16_as_ushort(hb) << 16);
}

template<int F>
__host__ __device__ constexpr int hdim(int l) {
    return (F == 0) ? 256 : ((F == 2) ? 512 : ((l % 2 == 0) ? 512 : 256));
}

// ---------------- prep: split fp32 weights into hi/lo bf16 blob ----------------
__global__ void split_weights(const float* __restrict__ Ws) {
    int id = blockIdx.x * 256 + threadIdx.x;        // 6*512*256
    int l  = id / (512 * 256);
    int r  = id - l * (512 * 256);
    int n  = r >> 8;
    int kp = r & 255;
    const float* W = Ws + ((size_t)l * 512 + n) * 512;
    float w0 = W[2 * kp], w1 = W[2 * kp + 1];
    __nv_bfloat16 h0 = __float2bfloat16(w0), h1 = __float2bfloat16(w1);
    __nv_bfloat16 l0 = __float2bfloat16(w0 - __bfloat162float(h0));
    __nv_bfloat16 l1 = __float2bfloat16(w1 - __bfloat162float(h1));
    int kt = kp >> 3, kpl = kp & 7;
    int pos = 2 * (kpl & 3) + (kpl >> 2);
    uint32_t base = (uint32_t)((l * 32 + kt) * 2) * 4096u + (uint32_t)(n * 8 + pos);
    gW[base]        = (uint32_t)__bfloat16_as_ushort(h0) | ((uint32_t)__bfloat16_as_ushort(h1) << 16);
    gW[base + 4096] = (uint32_t)__bfloat16_as_ushort(l0) | ((uint32_t)__bfloat16_as_ushort(l1) << 16);
}

// ---------------- layer 0 (K = 6) ----------------
template<int HOUT>
__device__ __noinline__ void layer0(uint8_t* sm,
    const float* __restrict__ inputs, const float* __restrict__ W_in,
    const float* __restrict__ b_in, const float* __restrict__ lnw,
    const float* __restrict__ lnb, int rowbase)
{
    uint32_t* actHi = (uint32_t*)(sm + SM_ACT_HI);
    uint32_t* actLo = (uint32_t*)(sm + SM_ACT_LO);
    float* sW    = (float*)(sm + SM_WBUF);
    float* sBias = (float*)(sm + SM_BIAS);
    float* sLw   = (float*)(sm + SM_LW);
    float* sLb   = (float*)(sm + SM_LB);
    float* xin   = (float*)(sm + SM_XIN);
    const int tid = threadIdx.x;

    for (int i = tid; i < HOUT * 6; i += NTHR) sW[i] = W_in[i];
    for (int i = tid; i < HOUT; i += NTHR) { sBias[i] = b_in[i]; sLw[i] = lnw[i]; sLb[i] = lnb[i]; }
    for (int i = tid; i < TMR * 6; i += NTHR) xin[i] = inputs[rowbase * 6 + i];
    __syncthreads();

    const int row = tid >> 2, cp = tid & 3;
    float x[6];
    #pragma unroll
    for (int k = 0; k < 6; ++k) x[k] = xin[row * 6 + k];

    float s = 0.f, q = 0.f;
    for (int nt = 0; nt < HOUT / 8; ++nt) {
        #pragma unroll
        for (int e = 0; e < 2; ++e) {
            int col = 8 * nt + 2 * cp + e;
            const float* w = sW + col * 6;
            float v = sBias[col];
            #pragma unroll
            for (int k = 0; k < 6; ++k) v += x[k] * w[k];
            s += v; q += v * v;
        }
    }
    s += __shfl_xor_sync(0xffffffffu, s, 1); q += __shfl_xor_sync(0xffffffffu, q, 1);
    s += __shfl_xor_sync(0xffffffffu, s, 2); q += __shfl_xor_sync(0xffffffffu, q, 2);
    const float mean = s * (1.0f / HOUT);
    const float rstd = rsqrtf(q * (1.0f / HOUT) - mean * mean + 1e-5f);

    for (int nt = 0; nt < HOUT / 8; ++nt) {
        float y[2];
        #pragma unroll
        for (int e = 0; e < 2; ++e) {
            int col = 8 * nt + 2 * cp + e;
            const float* w = sW + col * 6;
            float v = sBias[col];
            #pragma unroll
            for (int k = 0; k < 6; ++k) v += x[k] * w[k];
            y[e] = fmaxf((v - mean) * rstd * sLw[col] + sLb[col], 0.f);
        }
        uint32_t lo;
        uint32_t hi = pack_split(y[0], y[1], lo);
        uint32_t idx = (uint32_t)(nt * TMR + row) * 4u + (uint32_t)cp;
        actHi[idx] = hi; actLo[idx] = lo;
    }
    __syncthreads();
}

// ---------------- mid layer: HMMA 3-split GEMM + LN + ReLU (+ fused out) -------
template<int HIN, int HOUT, bool LAST>
__device__ __noinline__ void mid_layer(uint8_t* sm, int lane, int mb, int nh,
    int lidx, int fidx,
    const float* __restrict__ bias, const float* __restrict__ lnw,
    const float* __restrict__ lnb, const float* __restrict__ W_out,
    const float* __restrict__ b_out, float* __restrict__ out, int rowbase)
{
    constexpr int KT   = HIN / 16;
    constexpr int NT_W = HOUT / 16;     // n8-tiles per warp (half of HOUT/8)
    constexpr int CPW  = HOUT / 64;     // cp16 per thread per chunk

    uint32_t* actHi = (uint32_t*)(sm + SM_ACT_HI);
    uint32_t* actLo = (uint32_t*)(sm + SM_ACT_LO);
    uint32_t* wbuf  = (uint32_t*)(sm + SM_WBUF);
    float* sBias  = (float*)(sm + SM_BIAS);
    float* sLw    = (float*)(sm + SM_LW);
    float* sLb    = (float*)(sm + SM_LB);
    float* sWout  = (float*)(sm + SM_WOUT);
    float* red    = (float*)(sm + SM_RED);
    float* outAcc = (float*)(sm + SM_OUTACC);
    const int tid = threadIdx.x;

    for (int i = tid; i < HOUT; i += NTHR) { sBias[i] = bias[i]; sLw[i] = lnw[i]; sLb[i] = lnb[i]; }
    if (LAST)
        for (int i = tid; i < 3 * HOUT; i += NTHR)
            sWout[i] = W_out[(i / HOUT) * 512 + (i % HOUT)];

    auto stage = [&](int kt, int p) {
        const uint32_t* src = gW + (uint32_t)(lidx * 32 + kt) * 8192u;
        uint32_t* dst = wbuf + p * 8192;
        #pragma unroll
        for (int t = 0; t < CPW; ++t) {
            int u = (tid + t * NTHR) * 4;              // word in compact image (HOUT*16 words)
            int hl = u / (HOUT * 8);
            int rem = u - hl * (HOUT * 8);
            cp16(dst + hl * (HOUT * 8) + rem, src + hl * 4096 + rem);
        }
    };

    float acc[NT_W][4];
    #pragma unroll
    for (int t = 0; t < NT_W; ++t) { acc[t][0] = acc[t][1] = acc[t][2] = acc[t][3] = 0.f; }

    const int row0 = mb * 16 + (lane >> 2);
    const int cp   = lane & 3;
    const int ntb  = nh * NT_W;
    const uint32_t boff = (uint32_t)((lane >> 2) * 8 + 2 * cp);

    stage(0, 0); cp_commit();
    for (int kt = 0; kt < KT; ++kt) {
        cp_wait0();
        __syncthreads();
        if (kt + 1 < KT) { stage(kt + 1, (kt + 1) & 1); cp_commit(); }

        const uint32_t* B = wbuf + (kt & 1) * 8192;
        uint32_t i0 = (uint32_t)((2 * kt) * TMR + row0) * 4u + cp;
        uint32_t i1 = (uint32_t)((2 * kt) * TMR + row0 + 8) * 4u + cp;
        uint32_t i2 = (uint32_t)((2 * kt + 1) * TMR + row0) * 4u + cp;
        uint32_t i3 = (uint32_t)((2 * kt + 1) * TMR + row0 + 8) * 4u + cp;
        uint32_t ah0 = actHi[i0], ah1 = actHi[i1], ah2 = actHi[i2], ah3 = actHi[i3];
        uint32_t al0 = actLo[i0], al1 = actLo[i1], al2 = actLo[i2], al3 = actLo[i3];

        #pragma unroll
        for (int t = 0; t < NT_W; ++t) {
            const uint32_t* bp = B + (uint32_t)(ntb + t) * 64u + boff;
            uint2 bh = *(const uint2*)bp;
            uint2 bl = *(const uint2*)(bp + HOUT * 8);
            mma_bf16(acc[t][0], acc[t][1], acc[t][2], acc[t][3], ah0, ah1, ah2, ah3, bh.x, bh.y);
            mma_bf16(acc[t][0], acc[t][1], acc[t][2], acc[t][3], al0, al1, al2, al3, bh.x, bh.y);
            mma_bf16(acc[t][0], acc[t][1], acc[t][2], acc[t][3], ah0, ah1, ah2, ah3, bl.x, bl.y);
        }
    }

    // ---- epilogue ----
    float s0 = 0.f, q0 = 0.f, s1 = 0.f, q1 = 0.f;
    #pragma unroll
    for (int t = 0; t < NT_W; ++t) {
        float2 bv = *(const float2*)(sBias + 8 * (ntb + t) + 2 * cp);
        acc[t][0] += bv.x; acc[t][1] += bv.y; acc[t][2] += bv.x; acc[t][3] += bv.y;
        s0 += acc[t][0] + acc[t][1]; q0 += acc[t][0] * acc[t][0] + acc[t][1] * acc[t][1];
        s1 += acc[t][2] + acc[t][3]; q1 += acc[t][2] * acc[t][2] + acc[t][3] * acc[t][3];
    }
    #pragma unroll
    for (int o = 1; o <= 2; o <<= 1) {
        s0 += __shfl_xor_sync(0xffffffffu, s0, o); q0 += __shfl_xor_sync(0xffffffffu, q0, o);
        s1 += __shfl_xor_sync(0xffffffffu, s1, o); q1 += __shfl_xor_sync(0xffffffffu, q1, o);
    }
    if (cp == 0) {
        red[(nh * 64 + row0) * 2 + 0] = s0;      red[(nh * 64 + row0) * 2 + 1] = q0;
        red[(nh * 64 + row0 + 8) * 2 + 0] = s1;  red[(nh * 64 + row0 + 8) * 2 + 1] = q1;
    }
    __syncthreads();
    const float S0 = s0 + red[((nh ^ 1) * 64 + row0) * 2 + 0];
    const float Q0 = q0 + red[((nh ^ 1) * 64 + row0) * 2 + 1];
    const float S1 = s1 + red[((nh ^ 1) * 64 + row0 + 8) * 2 + 0];
    const float Q1 = q1 + red[((nh ^ 1) * 64 + row0 + 8) * 2 + 1];
    const float mean0 = S0 * (1.0f / HOUT);
    const float rstd0 = rsqrtf(Q0 * (1.0f / HOUT) - mean0 * mean0 + 1e-5f);
    const float mean1 = S1 * (1.0f / HOUT);
    const float rstd1 = rsqrtf(Q1 * (1.0f / HOUT) - mean1 * mean1 + 1e-5f);

    if (!LAST) {
        #pragma unroll
        for (int t = 0; t < NT_W; ++t) {
            int col0 = 8 * (ntb + t) + 2 * cp;
            float2 lwv = *(const float2*)(sLw + col0);
            float2 lbv = *(const float2*)(sLb + col0);
            float y00 = fmaxf((acc[t][0] - mean0) * rstd0 * lwv.x + lbv.x, 0.f);
            float y01 = fmaxf((acc[t][1] - mean0) * rstd0 * lwv.y + lbv.y, 0.f);
            float y10 = fmaxf((acc[t][2] - mean1) * rstd1 * lwv.x + lbv.x, 0.f);
            float y11 = fmaxf((acc[t][3] - mean1) * rstd1 * lwv.y + lbv.y, 0.f);
            uint32_t lo0, lo1;
            uint32_t hi0 = pack_split(y00, y01, lo0);
            uint32_t hi1 = pack_split(y10, y11, lo1);
            uint32_t idx0 = (uint32_t)((ntb + t) * TMR + row0) * 4u + cp;
            uint32_t idx1 = (uint32_t)((ntb + t) * TMR + row0 + 8) * 4u + cp;
            actHi[idx0] = hi0; actLo[idx0] = lo0;
            actHi[idx1] = hi1; actLo[idx1] = lo1;
        }
        __syncthreads();
    } else {
        float p0[3] = {0.f, 0.f, 0.f}, p1[3] = {0.f, 0.f, 0.f};
        #pragma unroll
        for (int t = 0; t < NT_W; ++t) {
            int col0 = 8 * (ntb + t) + 2 * cp;
            float2 lwv = *(const float2*)(sLw + col0);
            float2 lbv = *(const float2*)(sLb + col0);
            float y00 = fmaxf((acc[t][0] - mean0) * rstd0 * lwv.x + lbv.x, 0.f);
            float y01 = fmaxf((acc[t][1] - mean0) * rstd0 * lwv.y + lbv.y, 0.f);
            float y10 = fmaxf((acc[t][2] - mean1) * rstd1 * lwv.x + lbv.x, 0.f);
            float y11 = fmaxf((acc[t][3] - mean1) * rstd1 * lwv.y + lbv.y, 0.f);
            #pragma unroll
            for (int o = 0; o < 3; ++o) {
                float w0 = sWout[o * HOUT + col0], w1 = sWout[o * HOUT + col0 + 1];
                p0[o] += y00 * w0 + y01 * w1;
                p1[o] += y10 * w0 + y11 * w1;
            }
        }
        #pragma unroll
        for (int o = 0; o < 3; ++o) {
            #pragma unroll
            for (int m = 1; m <= 2; m <<= 1) {
                p0[o] += __shfl_xor_sync(0xffffffffu, p0[o], m);
                p1[o] += __shfl_xor_sync(0xffffffffu, p1[o], m);
            }
        }
        if (cp == 0) {
            #pragma unroll
            for (int o = 0; o < 3; ++o) {
                outAcc[nh * 192 + row0 * 3 + o] = p0[o];
                outAcc[nh * 192 + (row0 + 8) * 3 + o] = p1[o];
            }
        }
        __syncthreads();
        if (tid < 192) {
            int row = tid / 3, o = tid - row * 3;
            out[(size_t)(rowbase + row) * 9 + fidx * 3 + o] =
                outAcc[row * 3 + o] + outAcc[192 + row * 3 + o] + b_out[o];
        }
    }
}

// ---------------- fused kernel per factor ----------------
template<int F>
__global__ void __launch_bounds__(NTHR, 1) mipnet_tc(
    const float* __restrict__ inputs,
    const float* __restrict__ W_in, const float* __restrict__ b_in,
    const float* __restrict__ bs,
    const float* __restrict__ ln_w, const float* __restrict__ ln_b,
    const float* __restrict__ W_out, const float* __restrict__ b_out,
    float* __restrict__ out)
{
    extern __shared__ uint8_t sm[];
    const int tid  = threadIdx.x;
    const int lane = tid & 31;
    const int wid  = tid >> 5;
    const int mb   = wid & 3;
    const int nh   = wid >> 2;
    const int rowbase = blockIdx.x * TMR;

    layer0<hdim<F>(0)>(sm, inputs, W_in, b_in, ln_w, ln_b, rowbase);
    mid_layer<hdim<F>(0), hdim<F>(1), false>(sm, lane, mb, nh, 0, F, bs,
        ln_w + 512,  ln_b + 512,  W_out, b_out, out, rowbase);
    mid_layer<hdim<F>(1), hdim<F>(2), false>(sm, lane, mb, nh, 1, F, bs + 512,
        ln_w + 1024, ln_b + 1024, W_out, b_out, out, rowbase);
    mid_layer<hdim<F>(2), hdim<F>(3), false>(sm, lane, mb, nh, 2, F, bs + 1024,
        ln_w + 1536, ln_b + 1536, W_out, b_out, out, rowbase);
    mid_layer<hdim<F>(3), hdim<F>(4), false>(sm, lane, mb, nh, 3, F, bs + 1536,
        ln_w + 2048, ln_b + 2048, W_out, b_out, out, rowbase);
    mid_layer<hdim<F>(4), hdim<F>(5), false>(sm, lane, mb, nh, 4, F, bs + 2048,
        ln_w + 2560, ln_b + 2560, W_out, b_out, out, rowbase);
    mid_layer<hdim<F>(5), hdim<F>(6), true >(sm, lane, mb, nh, 5, F, bs + 2560,
        ln_w + 3072, ln_b + 3072, W_out, b_out, out, rowbase);
}

extern "C" void kernel_launch(void* const* d_in, const int* in_sizes, int n_in,
                              void* d_out, int out_size) {
    const float* inputs = (const float*)d_in[0];
    const float* W_in   = (const float*)d_in[1];
    const float* b_in   = (const float*)d_in[2];
    const float* Ws     = (const float*)d_in[3];
    const float* bs     = (const float*)d_in[4];
    const float* ln_w   = (const float*)d_in[5];
    const float* ln_b   = (const float*)d_in[6];
    const float* W_out  = (const float*)d_in[7];
    const float* b_out  = (const float*)d_in[8];
    float* out = (float*)d_out;

    const int Nrows = in_sizes[0] / 6;
    const int tiles = Nrows / TMR;      // 2048

    cudaFuncSetAttribute(mipnet_tc<0>, cudaFuncAttributeMaxDynamicSharedMemorySize, SM_TOTAL);
    cudaFuncSetAttribute(mipnet_tc<1>, cudaFuncAttributeMaxDynamicSharedMemorySize, SM_TOTAL);
    cudaFuncSetAttribute(mipnet_tc<2>, cudaFuncAttributeMaxDynamicSharedMemorySize, SM_TOTAL);

    split_weights<<<3072, 256>>>(Ws);

    mipnet_tc<0><<<tiles, NTHR, SM_TOTAL>>>(inputs, W_in, b_in, bs, ln_w, ln_b, W_out, b_out, out);
    mipnet_tc<1><<<tiles, NTHR, SM_TOTAL>>>(inputs, W_in, b_in, bs, ln_w, ln_b, W_out, b_out, out);
    mipnet_tc<2><<<tiles, NTHR, SM_TOTAL>>>(inputs, W_in, b_in, bs, ln_w, ln_b, W_out, b_out, out);
}